// round 15
// baseline (speedup 1.0000x reference)
#include <cuda_runtime.h>
#include <math.h>

#define BB 2
#define DIMC 96
#define INNER 192
#define NH 48
#define SS 576
#define GTOT (BB*SS)   // 1152
#define F3 (3*INNER)   // 576
#define NBH (BB*NH)    // 96

// Scratch (device globals; no allocation allowed)
__device__ float g_z[GTOT * INNER];
__device__ float g_xconv[GTOT * INNER];
__device__ float4 g_q4[NBH * SS];
__device__ float4 g_k4[NBH * SS];
__device__ float4 g_v4[NBH * SS];
__device__ float g_ig[NBH * SS];
__device__ float g_fg[NBH * SS];
__device__ float g_hstate[GTOT * INNER];   // (hnorm + skip*xconv)*silu(z)
__device__ float g_wupT[DIMC * 384];       // [c][o]
__device__ float g_wcgT[384 * 96];         // composed gates [f][2*jn+t]
__device__ float g_bg[96];                 // composed gate bias [2*jn+t]
__device__ float g_wdT[INNER * DIMC];      // [f][c]

#define NT_WUP  (DIMC*384)
#define NT_WCG  (384*96)
#define NT_WD   (INNER*DIMC)
#define NT_BIAS (96*32)
#define NT_ALL  (NT_WUP + NT_WCG + NT_WD + NT_BIAS)   // 95232

// ---------------------------------------------------------------------------
// kT: transposes + gate-weight composition (verbatim R14)
// ---------------------------------------------------------------------------
__global__ void kT(const float* __restrict__ w_up,
                   const float* __restrict__ w_q, const float* __restrict__ b_q,
                   const float* __restrict__ w_k, const float* __restrict__ b_k,
                   const float* __restrict__ w_v, const float* __restrict__ b_v,
                   const float* __restrict__ w_ig, const float* __restrict__ b_ig,
                   const float* __restrict__ w_fg, const float* __restrict__ b_fg,
                   const float* __restrict__ w_down) {
    int i = blockIdx.x * 256 + threadIdx.x;
    if (i < NT_WUP) {
        int c = i / 384, o = i % 384;
        g_wupT[c * 384 + o] = w_up[o * DIMC + c];
        return;
    }
    i -= NT_WUP;
    if (i < NT_WCG) {
        int f = i / 96, col = i % 96;
        int jn = col >> 1, t = col & 1;
        const float* wg = (t == 0) ? (w_ig + jn * F3) : (w_fg + jn * F3);
        float acc = 0.f;
        if (f < 192) {
            int n = f >> 2, d = f & 3;
#pragma unroll
            for (int o = 0; o < 4; o++) {
                acc += wg[4 * n + o]       * w_q[n * 16 + o * 4 + d];
                acc += wg[192 + 4 * n + o] * w_k[n * 16 + o * 4 + d];
            }
        } else {
            int fm = f - 192;
            int n = fm >> 2, d = fm & 3;
#pragma unroll
            for (int o = 0; o < 4; o++)
                acc += wg[384 + 4 * n + o] * w_v[n * 16 + o * 4 + d];
        }
        g_wcgT[f * 96 + col] = acc;
        return;
    }
    i -= NT_WCG;
    if (i < NT_WD) {
        int f = i / DIMC, c = i % DIMC;
        g_wdT[f * DIMC + c] = w_down[c * INNER + f];
        return;
    }
    i -= NT_WD;
    if (i < NT_BIAS) {
        int col = i >> 5, lane = i & 31;
        int jn = col >> 1, t = col & 1;
        const float* wg = (t == 0) ? (w_ig + jn * F3) : (w_fg + jn * F3);
        float acc = 0.f;
#pragma unroll
        for (int k = 0; k < 6; k++) {
            int o = lane + 32 * k;
            acc += wg[o] * b_q[o];
            acc += wg[192 + o] * b_k[o];
            acc += wg[384 + o] * b_v[o];
        }
#pragma unroll
        for (int off = 16; off > 0; off >>= 1)
            acc += __shfl_down_sync(0xffffffffu, acc, off);
        if (lane == 0)
            g_bg[col] = acc + ((t == 0) ? b_ig[jn] : b_fg[jn]);
    }
}

// ---------------------------------------------------------------------------
// K_A: LN + up-proj + conv + SiLU + qkv + composed gates. (verbatim R14)
// ---------------------------------------------------------------------------
__global__ void __launch_bounds__(384)
kA(const float* __restrict__ x,
   const float* __restrict__ ln_g,
   const float* __restrict__ ln_b,
   const float* __restrict__ b_up,
   const float* __restrict__ w_conv,
   const float* __restrict__ b_conv,
   const float* __restrict__ w_q, const float* __restrict__ b_q,
   const float* __restrict__ w_k, const float* __restrict__ b_k,
   const float* __restrict__ w_v, const float* __restrict__ b_v) {
    __shared__ __align__(16) float hT[DIMC][8];
    __shared__ float mu[7], iv[7];
    __shared__ __align__(16) float xim[7][INNER];
    __shared__ __align__(16) float xcv[4][INNER];
    __shared__ __align__(16) float part_i[4][8][48];
    __shared__ __align__(16) float part_f[4][8][48];
    const int g0 = blockIdx.x * 4;
    const int b = g0 / SS, sl0 = g0 % SS;
    const int tid = threadIdx.x;
    const int wid = tid >> 5, lane = tid & 31;

    for (int i = tid; i < 7 * DIMC; i += 384) {
        int hp = i / DIMC, c = i % DIMC;
        int sloc = sl0 - 3 + hp;
        hT[c][hp] = (sloc >= 0) ? x[(b * DIMC + c) * SS + sloc] : 0.f;
    }
    __syncthreads();
    if (wid < 7) {
        float sum = 0.f, sqv = 0.f;
        for (int c = lane; c < DIMC; c += 32) { float v = hT[c][wid]; sum += v; sqv += v * v; }
#pragma unroll
        for (int off = 16; off > 0; off >>= 1) {
            sum += __shfl_down_sync(0xffffffffu, sum, off);
            sqv += __shfl_down_sync(0xffffffffu, sqv, off);
        }
        if (lane == 0) {
            float m = sum * (1.f / DIMC);
            float var = sqv * (1.f / DIMC) - m * m;
            mu[wid] = m;
            iv[wid] = rsqrtf(var + 1e-5f);
        }
    }
    __syncthreads();
    for (int i = tid; i < 7 * DIMC; i += 384) {
        int hp = i / DIMC, c = i % DIMC;
        hT[c][hp] = (hT[c][hp] - mu[hp]) * iv[hp] * ln_g[c] + ln_b[c];
    }
    __syncthreads();

    if (tid < INNER) {
        const int o = tid;
        float acc[7];
        float bias = b_up[o];
#pragma unroll
        for (int p = 0; p < 7; p++) acc[p] = bias;
        for (int c = 0; c < DIMC; c++) {
            float w = g_wupT[c * 384 + o];
            float4 ha = *(const float4*)&hT[c][0];
            float4 hb = *(const float4*)&hT[c][4];
            acc[0] += w * ha.x; acc[1] += w * ha.y; acc[2] += w * ha.z;
            acc[3] += w * ha.w; acc[4] += w * hb.x; acc[5] += w * hb.y;
            acc[6] += w * hb.z;
        }
#pragma unroll
        for (int p = 0; p < 7; p++) xim[p][o] = acc[p];
    } else {
        const int o = tid;
        float acc[4];
        float bias = b_up[o];
#pragma unroll
        for (int p = 0; p < 4; p++) acc[p] = bias;
        for (int c = 0; c < DIMC; c++) {
            float w = g_wupT[c * 384 + o];
            float4 ha = *(const float4*)&hT[c][0];
            float4 hb = *(const float4*)&hT[c][4];
            acc[0] += w * ha.w; acc[1] += w * hb.x;
            acc[2] += w * hb.y; acc[3] += w * hb.z;
        }
#pragma unroll
        for (int p = 0; p < 4; p++)
            g_z[(g0 + p) * INNER + (o - INNER)] = acc[p];
    }
    __syncthreads();

    if (tid < 192) {
        const int p = tid / NH, n = tid % NH;
        float xc[4];
#pragma unroll
        for (int d = 0; d < 4; d++) xc[d] = b_conv[n * 4 + d];
#pragma unroll
        for (int k = 0; k < 4; k++) {
            if (sl0 + p - 3 + k >= 0) {
                const float* xr = &xim[p + k][n * 4];
#pragma unroll
                for (int d = 0; d < 4; d++)
                    xc[d] += w_conv[(n * 4 + d) * 4 + k] * xr[d];
            }
        }
#pragma unroll
        for (int d = 0; d < 4; d++) {
            float sg = 1.f / (1.f + __expf(-xc[d]));
            xc[d] *= sg;
        }
        float xm0 = xim[p + 3][n * 4], xm1 = xim[p + 3][n * 4 + 1];
        float xm2 = xim[p + 3][n * 4 + 2], xm3 = xim[p + 3][n * 4 + 3];

        float4 xcf = make_float4(xc[0], xc[1], xc[2], xc[3]);
        *(float4*)(&xcv[p][n * 4]) = xcf;
        *(float4*)(g_xconv + (g0 + p) * INNER + n * 4) = xcf;

        float q[4], kk[4], v[4];
#pragma unroll
        for (int o = 0; o < 4; o++) {
            const float* wq = w_q + n * 16 + o * 4;
            q[o] = b_q[n * 4 + o] + wq[0]*xc[0] + wq[1]*xc[1] + wq[2]*xc[2] + wq[3]*xc[3];
            const float* wk = w_k + n * 16 + o * 4;
            kk[o] = b_k[n * 4 + o] + wk[0]*xc[0] + wk[1]*xc[1] + wk[2]*xc[2] + wk[3]*xc[3];
            const float* wv = w_v + n * 16 + o * 4;
            v[o] = b_v[n * 4 + o] + wv[0]*xm0 + wv[1]*xm1 + wv[2]*xm2 + wv[3]*xm3;
        }
        int hidx = (b * NH + n) * SS + sl0 + p;
        g_q4[hidx] = make_float4(q[0], q[1], q[2], q[3]);
        g_k4[hidx] = make_float4(kk[0], kk[1], kk[2], kk[3]);
        g_v4[hidx] = make_float4(v[0], v[1], v[2], v[3]);
    }
    __syncthreads();

    {
        const int jn = tid % 48;
        const int slice = tid / 48;
        const int f0 = slice * 48;
        const float* act = (slice < 4) ? &xcv[0][f0] : &xim[3][f0 - 192];
        float ai[4], af[4];
#pragma unroll
        for (int p = 0; p < 4; p++) { ai[p] = 0.f; af[p] = 0.f; }
        for (int f = 0; f < 48; f++) {
            float2 wv = *(const float2*)&g_wcgT[(f0 + f) * 96 + 2 * jn];
#pragma unroll
            for (int p = 0; p < 4; p++) {
                float s = act[p * INNER + f];
                ai[p] += wv.x * s;
                af[p] += wv.y * s;
            }
        }
#pragma unroll
        for (int p = 0; p < 4; p++) { part_i[p][slice][jn] = ai[p]; part_f[p][slice][jn] = af[p]; }
    }
    __syncthreads();
    {
        const int r2 = tid % 96, p2 = tid / 96;
        bool ii = r2 < NH;
        int n2 = ii ? r2 : r2 - NH;
        float v = g_bg[2 * n2 + (ii ? 0 : 1)];
#pragma unroll
        for (int sl = 0; sl < 8; sl++)
            v += ii ? part_i[p2][sl][n2] : part_f[p2][sl][n2];
        float* dst = ii ? g_ig : g_fg;
        dst[(b * NH + n2) * SS + sl0 + p2] = v;
    }
}

// ---------------------------------------------------------------------------
// K_B v2: 288 threads, 2 consecutive positions per thread (work-efficient
// pair scans). Same math as R14, half the scan op-count.
// ---------------------------------------------------------------------------
__global__ void __launch_bounds__(288)
kB(const float* __restrict__ on_g,
   const float* __restrict__ on_b,
   const float* __restrict__ skip) {
    __shared__ float wsum[9], wmax[9];
    __shared__ float wtot[9][20];
    __shared__ float epre[9][20];
    const int bh = blockIdx.x;
    const int b = bh / NH, n = bh % NH;
    const int tid = threadIdx.x;              // 288
    const int wid = tid >> 5, lane = tid & 31; // 9 warps
    const int s0 = 2 * tid, s1 = s0 + 1;

    // ---- phase 1: sum scan of logsigmoid(fg) over pairs
    float fg0 = g_fg[bh * SS + s0], fg1 = g_fg[bh * SS + s1];
    float ig0 = g_ig[bh * SS + s0], ig1 = g_ig[bh * SS + s1];
    float lf0 = (fg0 > 0.f) ? -log1pf(__expf(-fg0)) : (fg0 - log1pf(__expf(fg0)));
    float lf1 = (fg1 > 0.f) ? -log1pf(__expf(-fg1)) : (fg1 - log1pf(__expf(fg1)));
    float pr = lf0 + lf1;
    float v = pr;
#pragma unroll
    for (int off = 1; off < 32; off <<= 1) {
        float nn = __shfl_up_sync(0xffffffffu, v, off);
        if (lane >= off) v += nn;
    }
    if (lane == 31) wsum[wid] = v;
    __syncthreads();
    float wex = 0.f;
    for (int ww = 0; ww < wid; ww++) wex += wsum[ww];
    const float excl = wex + (v - pr);
    const float cums0 = excl + lf0;
    const float cums1 = cums0 + lf1;
    const float a0 = ig0 - cums0, a1 = ig1 - cums1;

    // ---- phase 2: max scan of a over pairs; global max A
    float pm = fmaxf(a0, a1);
    float m = pm;
#pragma unroll
    for (int off = 1; off < 32; off <<= 1) {
        float nn = __shfl_up_sync(0xffffffffu, m, off);
        if (lane >= off) m = fmaxf(m, nn);
    }
    float mex_w = __shfl_up_sync(0xffffffffu, m, 1);
    if (lane == 0) mex_w = -1e30f;
    if (lane == 31) wmax[wid] = m;
    __syncthreads();
    float wexm = -1e30f;
    for (int ww = 0; ww < wid; ww++) wexm = fmaxf(wexm, wmax[ww]);
    const float base = fmaxf(wexm, mex_w);
    const float M0 = fmaxf(base, a0);
    const float M1 = fmaxf(base, pm);
    float A = -1e30f;
#pragma unroll
    for (int ww = 0; ww < 9; ww++) A = fmaxf(A, wmax[ww]);

    const float E0 = 0.5f * __expf(a0 - A);   // 0.5 = DH^-0.5 folded in
    const float E1 = 0.5f * __expf(a1 - A);

    // ---- phase 3: 20-component pair scan of (E*k⊗v, E*k)
    float4 q40 = g_q4[bh * SS + s0], k40 = g_k4[bh * SS + s0], v40 = g_v4[bh * SS + s0];
    float4 q41 = g_q4[bh * SS + s1], k41 = g_k4[bh * SS + s1], v41 = g_v4[bh * SS + s1];
    float kv0[4] = {k40.x, k40.y, k40.z, k40.w};
    float vv0[4] = {v40.x, v40.y, v40.z, v40.w};
    float kv1[4] = {k41.x, k41.y, k41.z, k41.w};
    float vv1[4] = {v41.x, v41.y, v41.z, v41.w};
    float st[20], op1[20];
#pragma unroll
    for (int j = 0; j < 4; j++) {
        float ek0 = E0 * kv0[j];
        st[16 + j] = ek0;
#pragma unroll
        for (int d = 0; d < 4; d++) st[j * 4 + d] = ek0 * vv0[d];
        float ek1 = E1 * kv1[j];
        op1[16 + j] = ek1;
#pragma unroll
        for (int d = 0; d < 4; d++) op1[j * 4 + d] = ek1 * vv1[d];
    }
#pragma unroll
    for (int c = 0; c < 20; c++) st[c] += op1[c];   // pair sum
#pragma unroll
    for (int off = 1; off < 32; off <<= 1) {
        float tmp[20];
#pragma unroll
        for (int c = 0; c < 20; c++) tmp[c] = __shfl_up_sync(0xffffffffu, st[c], off);
        if (lane >= off) {
#pragma unroll
            for (int c = 0; c < 20; c++) st[c] += tmp[c];
        }
    }
    if (lane == 31) {
#pragma unroll
        for (int c = 0; c < 20; c++) wtot[wid][c] = st[c];
    }
    __syncthreads();
    if (wid == 0 && lane < 20) {
        float acc = 0.f;
        for (int ww = 0; ww < 9; ww++) { epre[ww][lane] = acc; acc += wtot[ww][lane]; }
    }
    __syncthreads();
#pragma unroll
    for (int c = 0; c < 20; c++) st[c] += epre[wid][c];   // inclusive through s1
    // inclusive through s0 = st - op1

    const float4 og = *(const float4*)(on_g + n * 4);
    const float4 ob = *(const float4*)(on_b + n * 4);
    const float4 sk4 = *(const float4*)(skip + n * 4);

#pragma unroll
    for (int p = 0; p < 2; p++) {
        const int s = (p == 0) ? s0 : s1;
        const float M = (p == 0) ? M0 : M1;
        const float cums = (p == 0) ? cums0 : cums1;
        const float4 q4 = (p == 0) ? q40 : q41;
        float pre[20];
#pragma unroll
        for (int c = 0; c < 20; c++)
            pre[c] = (p == 0) ? (st[c] - op1[c]) : st[c];

        float qv[4] = {q4.x, q4.y, q4.z, q4.w};
        float o[4] = {0.f, 0.f, 0.f, 0.f};
        float csum = 0.f;
#pragma unroll
        for (int j = 0; j < 4; j++) {
            csum += qv[j] * pre[16 + j];
#pragma unroll
            for (int d = 0; d < 4; d++) o[d] += qv[j] * pre[j * 4 + d];
        }
        float norm = fmaxf(fabsf(csum), __expf(-(cums + A)));
        float denom = norm + 1e-6f * __expf(M - A);
        float inv = 1.f / denom;
        float h0 = o[0] * inv, h1 = o[1] * inv, h2 = o[2] * inv, h3 = o[3] * inv;

        float mm = (h0 + h1 + h2 + h3) * 0.25f;
        float d0 = h0 - mm, d1 = h1 - mm, d2 = h2 - mm, d3 = h3 - mm;
        float var = (d0*d0 + d1*d1 + d2*d2 + d3*d3) * 0.25f;
        float r = rsqrtf(var + 1e-5f);
        float hn0 = d0 * r * og.x + ob.x;
        float hn1 = d1 * r * og.y + ob.y;
        float hn2 = d2 * r * og.z + ob.z;
        float hn3 = d3 * r * og.w + ob.w;

        const int g = b * SS + s;
        float4 xc4 = *(const float4*)(g_xconv + g * INNER + n * 4);
        float4 z4  = *(const float4*)(g_z + g * INNER + n * 4);
        float sz0 = z4.x / (1.f + __expf(-z4.x));
        float sz1 = z4.y / (1.f + __expf(-z4.y));
        float sz2 = z4.z / (1.f + __expf(-z4.z));
        float sz3 = z4.w / (1.f + __expf(-z4.w));
        float4 outv = make_float4((hn0 + sk4.x * xc4.x) * sz0,
                                  (hn1 + sk4.y * xc4.y) * sz1,
                                  (hn2 + sk4.z * xc4.z) * sz2,
                                  (hn3 + sk4.w * xc4.w) * sz3);
        *(float4*)(g_hstate + g * INNER + n * 4) = outv;
    }
}

// ---------------------------------------------------------------------------
// K_C: down-proj + residual. (verbatim R14)
// ---------------------------------------------------------------------------
__global__ void kC(const float* __restrict__ x,
                   const float* __restrict__ b_down,
                   float* __restrict__ out) {
    __shared__ __align__(16) float hsT[INNER][4];
    __shared__ __align__(16) float part[4][4][100];
    const int g0 = blockIdx.x * 4;
    const int tid = threadIdx.x;            // 384
    {
        float2 hv = ((const float2*)(g_hstate + g0 * INNER))[tid];
        int i = tid * 2;
        int p = i / INNER, d = i % INNER;
        hsT[d][p] = hv.x;
        hsT[d + 1][p] = hv.y;
    }
    __syncthreads();

    const int c = tid % 96;
    const int slice = tid / 96;
    const int f0 = slice * 48;
    float acc[4];
#pragma unroll
    for (int p = 0; p < 4; p++) acc[p] = 0.f;
    for (int f = 0; f < 48; f++) {
        float w = g_wdT[(f0 + f) * DIMC + c];
        float4 hv = *(const float4*)&hsT[f0 + f][0];
        acc[0] += w * hv.x; acc[1] += w * hv.y;
        acc[2] += w * hv.z; acc[3] += w * hv.w;
    }
#pragma unroll
    for (int p = 0; p < 4; p++) part[p][slice][c] = acc[p];
    __syncthreads();

    const int b = g0 / SS, s0 = g0 % SS;
    {
        const int c2 = tid % 96, p2 = tid / 96;
        float v = part[p2][0][c2] + part[p2][1][c2] + part[p2][2][c2] + part[p2][3][c2]
                + b_down[c2];
        int gi = (b * DIMC + c2) * SS + s0 + p2;
        out[gi] = x[gi] + v;
    }
}

// ---------------------------------------------------------------------------
extern "C" void kernel_launch(void* const* d_in, const int* in_sizes, int n_in,
                              void* d_out, int out_size) {
    const float* x      = (const float*)d_in[0];
    const float* ln_g   = (const float*)d_in[1];
    const float* ln_b   = (const float*)d_in[2];
    const float* w_up   = (const float*)d_in[3];
    const float* b_up   = (const float*)d_in[4];
    const float* w_q    = (const float*)d_in[5];
    const float* b_q    = (const float*)d_in[6];
    const float* w_k    = (const float*)d_in[7];
    const float* b_k    = (const float*)d_in[8];
    const float* w_v    = (const float*)d_in[9];
    const float* b_v    = (const float*)d_in[10];
    const float* w_conv = (const float*)d_in[11];
    const float* b_conv = (const float*)d_in[12];
    const float* w_ig   = (const float*)d_in[13];
    const float* b_ig   = (const float*)d_in[14];
    const float* w_fg   = (const float*)d_in[15];
    const float* b_fg   = (const float*)d_in[16];
    const float* on_g   = (const float*)d_in[17];
    const float* on_b   = (const float*)d_in[18];
    const float* skip   = (const float*)d_in[19];
    const float* w_down = (const float*)d_in[20];
    const float* b_down = (const float*)d_in[21];
    float* out = (float*)d_out;

    kT<<<(NT_ALL + 255) / 256, 256>>>(w_up, w_q, b_q, w_k, b_k, w_v, b_v,
                                      w_ig, b_ig, w_fg, b_fg, w_down);
    kA<<<GTOT / 4, 384>>>(x, ln_g, ln_b, b_up, w_conv, b_conv,
                          w_q, b_q, w_k, b_k, w_v, b_v);
    kB<<<NBH, 288>>>(on_g, on_b, skip);
    kC<<<GTOT / 4, 384>>>(x, b_down, out);
}